// round 7
// baseline (speedup 1.0000x reference)
#include <cuda_runtime.h>
#include <cuda_fp16.h>
#include <cstdint>

// ----------------------------------------------------------------------------
// AdaAffcell, warp-specialized persistent kernel (sm_103 base ISA, HMMA).
//   hx = [h, x] (B x 256); g = hx W_g^T + b_g ; z = hx W_a^T + b_a
//   h~ = sigmoid(g)*tanh(z) + (1-sigmoid(g))*z ; out = LN(h~)*gamma + beta
//
// 384 threads: warps 0..7 = consumers (MMA + epilogue), warps 8..11 =
// producers (LDG fp32 -> fp16 -> STS into a 2-deep A-buffer ring).
// Handshake via named barriers: FULL[p]=1+p, EMPTY[p]=3+p (count 384),
// consumer-only stats barrier id 5 (count 256). W in SMEM once per CTA.
// ----------------------------------------------------------------------------

#define NROWS  524288
#define TILE   64
#define NTILES (NROWS / TILE)
#define EPSV   1e-5f

__device__ __align__(16) __half g_Wimg[256 * 264];

// SMEM layout (bytes)
#define SMEM_W     0            // fp16 [256][264] = 135168
#define SMEM_A0    135168       // fp16 [64][264]  =  33792
#define SMEM_A1    168960       // fp16 [64][264]  =  33792
#define SMEM_BG    202752       // f32 [128]
#define SMEM_BA    203264
#define SMEM_GAM   203776
#define SMEM_BET   204288
#define SMEM_PS    204800       // f32 [2][64][5]  = 2560 (sum, parity-buffered)
#define SMEM_PQ    207360       // f32 [2][64][5]  = 2560 (sumsq)
#define SMEM_TOTAL 209920

#define BAR_SYNC(id, cnt)   asm volatile("bar.sync %0, %1;"   :: "r"(id), "r"(cnt) : "memory")
#define BAR_ARRIVE(id, cnt) asm volatile("bar.arrive %0, %1;" :: "r"(id), "r"(cnt) : "memory")

static __device__ __forceinline__ uint32_t smem_u32(const void* p) {
    uint32_t a;
    asm("{ .reg .u64 t; cvta.to.shared.u64 t, %1; cvt.u32.u64 %0, t; }"
        : "=r"(a) : "l"(p));
    return a;
}

static __device__ __forceinline__ float tanh_fast(float v) {
    float r;
    asm("tanh.approx.f32 %0, %1;" : "=f"(r) : "f"(v));
    return r;
}

#define LDSM4(r0, r1, r2, r3, addr)                                              \
    asm volatile("ldmatrix.sync.aligned.m8n8.x4.shared.b16 {%0,%1,%2,%3}, [%4];" \
                 : "=r"(r0), "=r"(r1), "=r"(r2), "=r"(r3) : "r"(addr))

#define MMA16816(c, a0, a1, a2, a3, b0, b1)                                  \
    asm volatile("mma.sync.aligned.m16n8k16.row.col.f32.f16.f16.f32 "        \
                 "{%0,%1,%2,%3}, {%4,%5,%6,%7}, {%8,%9}, {%0,%1,%2,%3};"     \
                 : "+f"((c)[0]), "+f"((c)[1]), "+f"((c)[2]), "+f"((c)[3])    \
                 : "r"(a0), "r"(a1), "r"(a2), "r"(a3), "r"(b0), "r"(b1))

// ---------------------------------------------------------------------------
__global__ void prep_w_kernel(const float* __restrict__ Wa, const float* __restrict__ Wg) {
    int i = blockIdx.x * 256 + threadIdx.x;   // 0..65535
    int n = i >> 8;
    int k = i & 255;
    float v = (n < 128) ? Wg[n * 256 + k] : Wa[(n - 128) * 256 + k];
    g_Wimg[n * 264 + k] = __float2half_rn(v);
}

// ---------------------------------------------------------------------------
__global__ void __launch_bounds__(384, 1) adaaff_kernel(
    const float* __restrict__ x, const float* __restrict__ h,
    const float* __restrict__ b_a, const float* __restrict__ b_g,
    const float* __restrict__ gamma, const float* __restrict__ beta,
    float* __restrict__ out)
{
    extern __shared__ __align__(16) char smem[];
    const uint32_t smem_base = smem_u32(smem);
    const int tid  = threadIdx.x;
    const int lane = tid & 31;
    const int wid  = tid >> 5;

    // ---- one-time setup (all 384 threads): vectors + W tile ----
    if (tid < 128) {
        *(float*)(smem + SMEM_BG  + tid * 4) = b_g[tid];
        *(float*)(smem + SMEM_BA  + tid * 4) = b_a[tid];
        *(float*)(smem + SMEM_GAM + tid * 4) = gamma[tid];
        *(float*)(smem + SMEM_BET + tid * 4) = beta[tid];
    }
    {
        const uint4* src = (const uint4*)g_Wimg;
        uint4* dst = (uint4*)(smem + SMEM_W);
        for (int i = tid; i < 8448; i += 384) dst[i] = src[i];
    }
    __syncthreads();

    if (wid >= 8) {
        // ===================== PRODUCER (warps 8..11) =====================
        const int ptid = tid - 256;            // 0..127
        const int pm0  = ptid >> 5;            // 0..3
        const int pk0  = (ptid & 31) << 2;

        int p = 0, it = 0;
        for (int t = blockIdx.x; t < NTILES; t += gridDim.x, p ^= 1, it++) {
            if (it >= 2) BAR_SYNC(3 + p, 384);          // wait: buffer p freed
            const size_t r0 = (size_t)t * TILE;
            __half* sA = (__half*)(smem + (p ? SMEM_A1 : SMEM_A0));
            #pragma unroll
            for (int q = 0; q < 2; q++) {               // 2 passes of 32 rows
                float4 vh[8], vx[8];
                #pragma unroll
                for (int j = 0; j < 8; j++) {
                    const size_t m = r0 + pm0 + j * 4 + q * 32;
                    vh[j] = *(const float4*)&h[m * 128 + pk0];
                    vx[j] = *(const float4*)&x[m * 128 + pk0];
                }
                #pragma unroll
                for (int j = 0; j < 8; j++) {
                    const int m = pm0 + j * 4 + q * 32;
                    __half2 p0 = __floats2half2_rn(vh[j].x, vh[j].y);
                    __half2 p1 = __floats2half2_rn(vh[j].z, vh[j].w);
                    *(uint2*)&sA[m * 264 + pk0] =
                        make_uint2(*(uint32_t*)&p0, *(uint32_t*)&p1);
                    __half2 q0 = __floats2half2_rn(vx[j].x, vx[j].y);
                    __half2 q1 = __floats2half2_rn(vx[j].z, vx[j].w);
                    *(uint2*)&sA[m * 264 + 128 + pk0] =
                        make_uint2(*(uint32_t*)&q0, *(uint32_t*)&q1);
                }
            }
            asm volatile("membar.cta;" ::: "memory");   // STS visible before arrive
            BAR_ARRIVE(1 + p, 384);                     // buffer p full
        }
    } else {
        // ===================== CONSUMER (warps 0..7) ======================
        const int wm  = wid & 1;       // 32-row block
        const int wn  = wid >> 1;      // 32-feature block (0..3)
        const int tig = lane & 3;
        const int gq  = lane >> 2;

        uint32_t a_off[2];
        #pragma unroll
        for (int i = 0; i < 2; i++) {
            int r  = wm * 32 + 16 * i + (lane & 15);
            int kq = (lane >> 4) * 8;
            a_off[i] = (uint32_t)(r * 264 + kq) * 2;
        }
        uint32_t b_addr[4];
        #pragma unroll
        for (int j2 = 0; j2 < 4; j2++) {
            int nb = wn * 32 + (j2 & 1) * 16 + (j2 >> 1) * 128;
            int n  = nb + (lane & 7) + ((lane >> 4) & 1) * 8;
            int kq = ((lane >> 3) & 1) * 8;
            b_addr[j2] = smem_base + SMEM_W + (uint32_t)(n * 264 + kq) * 2;
        }

        float* s_bg  = (float*)(smem + SMEM_BG);
        float* s_ba  = (float*)(smem + SMEM_BA);
        float* s_gam = (float*)(smem + SMEM_GAM);
        float* s_bet = (float*)(smem + SMEM_BET);

        int p = 0;
        for (int t = blockIdx.x; t < NTILES; t += gridDim.x, p ^= 1) {
            BAR_SYNC(1 + p, 384);                      // wait: buffer p full

            const uint32_t a_base = smem_base + (p ? SMEM_A1 : SMEM_A0);
            float c[2][8][4];
            #pragma unroll
            for (int i = 0; i < 2; i++)
                #pragma unroll
                for (int j = 0; j < 8; j++)
                    #pragma unroll
                    for (int e = 0; e < 4; e++) c[i][j][e] = 0.0f;

            #pragma unroll
            for (int s = 0; s < 16; s++) {
                const uint32_t ko = (uint32_t)s * 32;
                uint32_t ar[2][4], br[4][4];
                #pragma unroll
                for (int i = 0; i < 2; i++)
                    LDSM4(ar[i][0], ar[i][1], ar[i][2], ar[i][3], a_base + a_off[i] + ko);
                #pragma unroll
                for (int j2 = 0; j2 < 4; j2++)
                    LDSM4(br[j2][0], br[j2][1], br[j2][2], br[j2][3], b_addr[j2] + ko);
                #pragma unroll
                for (int i = 0; i < 2; i++) {
                    #pragma unroll
                    for (int j = 0; j < 8; j++) {
                        const int j2  = (j >> 2) * 2 + ((j & 3) >> 1);
                        const int sub = (j & 1) * 2;
                        MMA16816(c[i][j], ar[i][0], ar[i][1], ar[i][2], ar[i][3],
                                 br[j2][sub], br[j2][sub + 1]);
                    }
                }
            }

            // ---- activation (forces MMA completion), then release buffer ----
            float rsum[4] = {0.f, 0.f, 0.f, 0.f};
            float rsq[4]  = {0.f, 0.f, 0.f, 0.f};
            #pragma unroll
            for (int i = 0; i < 2; i++) {
                #pragma unroll
                for (int j = 0; j < 4; j++) {
                    const int f0 = wn * 32 + j * 8 + 2 * tig;
                    #pragma unroll
                    for (int rh = 0; rh < 2; rh++) {
                        #pragma unroll
                        for (int e = 0; e < 2; e++) {
                            const int f = f0 + e;
                            float gv = c[i][j][rh * 2 + e] + s_bg[f];
                            float zv = c[i][j + 4][rh * 2 + e] + s_ba[f];
                            float al = 0.5f + 0.5f * tanh_fast(0.5f * gv);
                            float ht = al * tanh_fast(zv) + (1.0f - al) * zv;
                            c[i][j][rh * 2 + e] = ht;
                            rsum[i * 2 + rh] += ht;
                            rsq[i * 2 + rh]  += ht * ht;
                        }
                    }
                }
            }
            BAR_ARRIVE(3 + p, 384);                    // buffer p consumed

            // ---- row statistics (parity-buffered psum) ----
            float* s_ps = (float*)(smem + SMEM_PS) + p * 320;
            float* s_pq = (float*)(smem + SMEM_PQ) + p * 320;
            #pragma unroll
            for (int r = 0; r < 4; r++) {
                float sv = rsum[r], qv = rsq[r];
                sv += __shfl_xor_sync(0xffffffffu, sv, 1);
                qv += __shfl_xor_sync(0xffffffffu, qv, 1);
                sv += __shfl_xor_sync(0xffffffffu, sv, 2);
                qv += __shfl_xor_sync(0xffffffffu, qv, 2);
                if (tig == 0) {
                    const int rowl = wm * 32 + 16 * (r >> 1) + 8 * (r & 1) + gq;
                    s_ps[rowl * 5 + wn] = sv;
                    s_pq[rowl * 5 + wn] = qv;
                }
            }
            BAR_SYNC(5, 256);                          // consumers only

            // ---- normalize + store (mu/rstd computed inline per thread) ----
            const size_t r0 = (size_t)t * TILE;
            #pragma unroll
            for (int i = 0; i < 2; i++) {
                #pragma unroll
                for (int rh = 0; rh < 2; rh++) {
                    const int rowl = wm * 32 + 16 * i + 8 * rh + gq;
                    float sv = 0.f, qv = 0.f;
                    #pragma unroll
                    for (int w = 0; w < 4; w++) {
                        sv += s_ps[rowl * 5 + w];
                        qv += s_pq[rowl * 5 + w];
                    }
                    const float mu = sv * (1.0f / 128.0f);
                    const float rs = rsqrtf(qv * (1.0f / 128.0f) - mu * mu + EPSV);
                    #pragma unroll
                    for (int j = 0; j < 4; j++) {
                        const int f0 = wn * 32 + j * 8 + 2 * tig;
                        float2 v;
                        v.x = (c[i][j][rh * 2 + 0] - mu) * rs * s_gam[f0]     + s_bet[f0];
                        v.y = (c[i][j][rh * 2 + 1] - mu) * rs * s_gam[f0 + 1] + s_bet[f0 + 1];
                        *(float2*)&out[(r0 + rowl) * 128 + f0] = v;
                    }
                }
            }
        }
    }
}

// ---------------------------------------------------------------------------
extern "C" void kernel_launch(void* const* d_in, const int* in_sizes, int n_in,
                              void* d_out, int out_size) {
    const float* x     = (const float*)d_in[0];
    const float* h     = (const float*)d_in[1];
    const float* W_a   = (const float*)d_in[2];
    const float* W_g   = (const float*)d_in[3];
    const float* b_a   = (const float*)d_in[4];
    const float* b_g   = (const float*)d_in[5];
    const float* gamma = (const float*)d_in[6];
    const float* beta  = (const float*)d_in[7];
    float* out = (float*)d_out;

    static int nsm = 0;
    if (nsm == 0) {
        int dev = 0, v = 0;
        nsm = 148;
        if (cudaGetDevice(&dev) == cudaSuccess &&
            cudaDeviceGetAttribute(&v, cudaDevAttrMultiProcessorCount, dev) == cudaSuccess &&
            v > 0)
            nsm = v;
        cudaFuncSetAttribute(adaaff_kernel,
                             cudaFuncAttributeMaxDynamicSharedMemorySize, SMEM_TOTAL);
    }

    prep_w_kernel<<<256, 256>>>(W_a, W_g);
    adaaff_kernel<<<nsm, 384, SMEM_TOTAL>>>(x, h, b_a, b_g, gamma, beta, out);
}

// round 8
// speedup vs baseline: 1.0523x; 1.0523x over previous
#include <cuda_runtime.h>
#include <cuda_fp16.h>
#include <cstdint>

// ----------------------------------------------------------------------------
// AdaAffcell, persistent-CTA pipelined (sm_103 base ISA: HMMA mma.sync).
//   hx = [h, x] (B x 256); g = hx W_g^T + b_g ; z = hx W_a^T + b_a
//   h~ = sigmoid(g)*tanh(z) + (1-sigmoid(g))*z ; out = LN(h~)*gamma + beta
//
// R6 integrated structure (register-staged double buffer, W resident) with a
// 16-warp partition: 512 threads, warp grid (wm=2, wn=8). Each warp owns
// 32 rows x (16 g-cols + 16 matching z-cols): 32 acc regs + 32 staging regs
// + 16 frag regs ~= 110 regs -> fits the 128-reg/512-thread budget while
// doubling warps/SMSP (2 -> 4) to cover LDS/MUFU/barrier latency.
// ----------------------------------------------------------------------------

#define NROWS  524288
#define TILE   64
#define NTILES (NROWS / TILE)
#define EPSV   1e-5f

// fp16 image of Wcat = [W_g ; W_a], padded stride 264 halves.
__device__ __align__(16) __half g_Wimg[256 * 264];

// SMEM layout (bytes)
#define SMEM_W     0            // fp16 [256][264] = 135168
#define SMEM_A0    135168       // fp16 [64][264]  =  33792
#define SMEM_A1    168960       // fp16 [64][264]  =  33792
#define SMEM_BG    202752       // f32 [128]
#define SMEM_BA    203264
#define SMEM_GAM   203776
#define SMEM_BET   204288
#define SMEM_PSUM  204800       // f32 [64][9] = 2304
#define SMEM_PSQ   207104       // f32 [64][9] = 2304
#define SMEM_MU    209408       // f32 [64]
#define SMEM_RSTD  209664       // f32 [64]
#define SMEM_TOTAL 209920

static __device__ __forceinline__ uint32_t smem_u32(const void* p) {
    uint32_t a;
    asm("{ .reg .u64 t; cvta.to.shared.u64 t, %1; cvt.u32.u64 %0, t; }"
        : "=r"(a) : "l"(p));
    return a;
}

static __device__ __forceinline__ float tanh_fast(float v) {
    float r;
    asm("tanh.approx.f32 %0, %1;" : "=f"(r) : "f"(v));
    return r;
}

#define LDSM4(r0, r1, r2, r3, addr)                                              \
    asm volatile("ldmatrix.sync.aligned.m8n8.x4.shared.b16 {%0,%1,%2,%3}, [%4];" \
                 : "=r"(r0), "=r"(r1), "=r"(r2), "=r"(r3) : "r"(addr))

#define MMA16816(c, a0, a1, a2, a3, b0, b1)                                  \
    asm volatile("mma.sync.aligned.m16n8k16.row.col.f32.f16.f16.f32 "        \
                 "{%0,%1,%2,%3}, {%4,%5,%6,%7}, {%8,%9}, {%0,%1,%2,%3};"     \
                 : "+f"((c)[0]), "+f"((c)[1]), "+f"((c)[2]), "+f"((c)[3])    \
                 : "r"(a0), "r"(a1), "r"(a2), "r"(a3), "r"(b0), "r"(b1))

// ---------------------------------------------------------------------------
__global__ void prep_w_kernel(const float* __restrict__ Wa, const float* __restrict__ Wg) {
    int i = blockIdx.x * 256 + threadIdx.x;   // 0..65535
    int n = i >> 8;
    int k = i & 255;
    float v = (n < 128) ? Wg[n * 256 + k] : Wa[(n - 128) * 256 + k];
    g_Wimg[n * 264 + k] = __float2half_rn(v);
}

// ---------------------------------------------------------------------------
__global__ void __launch_bounds__(512, 1) adaaff_kernel(
    const float* __restrict__ x, const float* __restrict__ h,
    const float* __restrict__ b_a, const float* __restrict__ b_g,
    const float* __restrict__ gamma, const float* __restrict__ beta,
    float* __restrict__ out)
{
    extern __shared__ __align__(16) char smem[];
    const uint32_t smem_base = smem_u32(smem);
    const int tid  = threadIdx.x;
    const int lane = tid & 31;
    const int wid  = tid >> 5;
    const int wm   = wid & 1;      // 32-row block
    const int wn   = wid >> 1;     // 16-feature block (0..7)
    const int tig  = lane & 3;
    const int gq   = lane >> 2;

    // ---- one-time setup: vectors + W tile ----
    if (tid < 128) {
        *(float*)(smem + SMEM_BG  + tid * 4) = b_g[tid];
        *(float*)(smem + SMEM_BA  + tid * 4) = b_a[tid];
        *(float*)(smem + SMEM_GAM + tid * 4) = gamma[tid];
        *(float*)(smem + SMEM_BET + tid * 4) = beta[tid];
    }
    {
        const uint4* src = (const uint4*)g_Wimg;
        uint4* dst = (uint4*)(smem + SMEM_W);
        for (int i = tid; i < 8448; i += 512) dst[i] = src[i];
    }

    // staging coords: i = tid + j*512 -> m = (tid>>5) + j*16, k0 = (tid&31)*4
    const int sm0 = tid >> 5;
    const int sk0 = (tid & 31) << 2;

    float4 rh4[4], rx4[4];

    // ---- prologue: load + store tile #blockIdx.x into buffer 0 ----
    int tile = blockIdx.x;
    if (tile < NTILES) {
        const size_t r0 = (size_t)tile * TILE;
        #pragma unroll
        for (int j = 0; j < 4; j++) {
            const size_t m = r0 + sm0 + j * 16;
            rh4[j] = *(const float4*)&h[m * 128 + sk0];
            rx4[j] = *(const float4*)&x[m * 128 + sk0];
        }
        __half* sA = (__half*)(smem + SMEM_A0);
        #pragma unroll
        for (int j = 0; j < 4; j++) {
            const int m = sm0 + j * 16;
            __half2 p0 = __floats2half2_rn(rh4[j].x, rh4[j].y);
            __half2 p1 = __floats2half2_rn(rh4[j].z, rh4[j].w);
            *(uint2*)&sA[m * 264 + sk0] = make_uint2(*(uint32_t*)&p0, *(uint32_t*)&p1);
            __half2 q0 = __floats2half2_rn(rx4[j].x, rx4[j].y);
            __half2 q1 = __floats2half2_rn(rx4[j].z, rx4[j].w);
            *(uint2*)&sA[m * 264 + 128 + sk0] = make_uint2(*(uint32_t*)&q0, *(uint32_t*)&q1);
        }
    }
    __syncthreads();

    // ldmatrix lane addressing.
    uint32_t a_off[2];
    #pragma unroll
    for (int i = 0; i < 2; i++) {
        int r  = wm * 32 + 16 * i + (lane & 15);
        int kq = (lane >> 4) * 8;
        a_off[i] = (uint32_t)(r * 264 + kq) * 2;
    }
    // B: j2=0 -> g cols (wn*16), j2=1 -> z cols (wn*16 + 128)
    uint32_t b_addr[2];
    #pragma unroll
    for (int j2 = 0; j2 < 2; j2++) {
        int nb = wn * 16 + j2 * 128;
        int n  = nb + (lane & 7) + ((lane >> 4) & 1) * 8;
        int kq = ((lane >> 3) & 1) * 8;
        b_addr[j2] = smem_base + SMEM_W + (uint32_t)(n * 264 + kq) * 2;
    }

    float* s_bg   = (float*)(smem + SMEM_BG);
    float* s_ba   = (float*)(smem + SMEM_BA);
    float* s_gam  = (float*)(smem + SMEM_GAM);
    float* s_bet  = (float*)(smem + SMEM_BET);
    float* s_psum = (float*)(smem + SMEM_PSUM);
    float* s_psq  = (float*)(smem + SMEM_PSQ);
    float* s_mu   = (float*)(smem + SMEM_MU);
    float* s_rstd = (float*)(smem + SMEM_RSTD);

    int p = 0;
    while (tile < NTILES) {
        const int ntile = tile + gridDim.x;
        const bool has_next = (ntile < NTILES);

        // ---- 1. issue next tile's GMEM loads ----
        if (has_next) {
            const size_t r0 = (size_t)ntile * TILE;
            #pragma unroll
            for (int j = 0; j < 4; j++) {
                const size_t m = r0 + sm0 + j * 16;
                rh4[j] = *(const float4*)&h[m * 128 + sk0];
                rx4[j] = *(const float4*)&x[m * 128 + sk0];
            }
        }

        // ---- 2. MMA on current buffer ----
        // c[i][j]: i = m16 block; j 0,1 = g n8 blocks, j 2,3 = matching z
        const uint32_t a_base = smem_base + (p ? SMEM_A1 : SMEM_A0);
        float c[2][4][4];
        #pragma unroll
        for (int i = 0; i < 2; i++)
            #pragma unroll
            for (int j = 0; j < 4; j++)
                #pragma unroll
                for (int e = 0; e < 4; e++) c[i][j][e] = 0.0f;

        #pragma unroll
        for (int s = 0; s < 16; s++) {
            const uint32_t ko = (uint32_t)s * 32;
            uint32_t ar[2][4], br[2][4];
            #pragma unroll
            for (int i = 0; i < 2; i++)
                LDSM4(ar[i][0], ar[i][1], ar[i][2], ar[i][3], a_base + a_off[i] + ko);
            #pragma unroll
            for (int j2 = 0; j2 < 2; j2++)
                LDSM4(br[j2][0], br[j2][1], br[j2][2], br[j2][3], b_addr[j2] + ko);
            #pragma unroll
            for (int i = 0; i < 2; i++) {
                #pragma unroll
                for (int j = 0; j < 4; j++) {
                    const int j2  = j >> 1;          // 0,0,1,1
                    const int sub = (j & 1) * 2;
                    MMA16816(c[i][j], ar[i][0], ar[i][1], ar[i][2], ar[i][3],
                             br[j2][sub], br[j2][sub + 1]);
                }
            }
        }

        // ---- 3. publish next A tile into spare buffer (before stats barrier) ----
        if (has_next) {
            __half* sA = (__half*)(smem + (p ? SMEM_A0 : SMEM_A1));
            #pragma unroll
            for (int j = 0; j < 4; j++) {
                const int m = sm0 + j * 16;
                __half2 p0 = __floats2half2_rn(rh4[j].x, rh4[j].y);
                __half2 p1 = __floats2half2_rn(rh4[j].z, rh4[j].w);
                *(uint2*)&sA[m * 264 + sk0] = make_uint2(*(uint32_t*)&p0, *(uint32_t*)&p1);
                __half2 q0 = __floats2half2_rn(rx4[j].x, rx4[j].y);
                __half2 q1 = __floats2half2_rn(rx4[j].z, rx4[j].w);
                *(uint2*)&sA[m * 264 + 128 + sk0] = make_uint2(*(uint32_t*)&q0, *(uint32_t*)&q1);
            }
        }

        // ---- 4. epilogue: gate+tanh in regs, row stats via SMEM ----
        float rsum[4] = {0.f, 0.f, 0.f, 0.f};
        float rsq[4]  = {0.f, 0.f, 0.f, 0.f};
        #pragma unroll
        for (int i = 0; i < 2; i++) {
            #pragma unroll
            for (int j = 0; j < 2; j++) {
                const int f0 = wn * 16 + j * 8 + 2 * tig;
                #pragma unroll
                for (int rh = 0; rh < 2; rh++) {
                    #pragma unroll
                    for (int e = 0; e < 2; e++) {
                        const int f = f0 + e;
                        float gv = c[i][j][rh * 2 + e] + s_bg[f];
                        float zv = c[i][j + 2][rh * 2 + e] + s_ba[f];
                        float al = 0.5f + 0.5f * tanh_fast(0.5f * gv);   // sigmoid
                        float ht = al * tanh_fast(zv) + (1.0f - al) * zv;
                        c[i][j][rh * 2 + e] = ht;
                        rsum[i * 2 + rh] += ht;
                        rsq[i * 2 + rh]  += ht * ht;
                    }
                }
            }
        }
        #pragma unroll
        for (int r = 0; r < 4; r++) {
            float sv = rsum[r], qv = rsq[r];
            sv += __shfl_xor_sync(0xffffffffu, sv, 1);
            qv += __shfl_xor_sync(0xffffffffu, qv, 1);
            sv += __shfl_xor_sync(0xffffffffu, sv, 2);
            qv += __shfl_xor_sync(0xffffffffu, qv, 2);
            if (tig == 0) {
                const int rowl = wm * 32 + 16 * (r >> 1) + 8 * (r & 1) + gq;
                s_psum[rowl * 9 + wn] = sv;
                s_psq[rowl * 9 + wn]  = qv;
            }
        }
        __syncthreads();          // covers psum/psq AND spare-A publication

        if (tid < 64) {
            float sv = 0.f, qv = 0.f;
            #pragma unroll
            for (int w = 0; w < 8; w++) { sv += s_psum[tid * 9 + w]; qv += s_psq[tid * 9 + w]; }
            const float mu  = sv * (1.0f / 128.0f);
            const float var = qv * (1.0f / 128.0f) - mu * mu;
            s_mu[tid]   = mu;
            s_rstd[tid] = rsqrtf(var + EPSV);
        }
        __syncthreads();

        // normalize + store
        {
            const size_t r0 = (size_t)tile * TILE;
            #pragma unroll
            for (int i = 0; i < 2; i++) {
                #pragma unroll
                for (int rh = 0; rh < 2; rh++) {
                    const int rowl = wm * 32 + 16 * i + 8 * rh + gq;
                    const float mu = s_mu[rowl];
                    const float rs = s_rstd[rowl];
                    #pragma unroll
                    for (int j = 0; j < 2; j++) {
                        const int f0 = wn * 16 + j * 8 + 2 * tig;
                        float2 v;
                        v.x = (c[i][j][rh * 2 + 0] - mu) * rs * s_gam[f0]     + s_bet[f0];
                        v.y = (c[i][j][rh * 2 + 1] - mu) * rs * s_gam[f0 + 1] + s_bet[f0 + 1];
                        *(float2*)&out[(r0 + rowl) * 128 + f0] = v;
                    }
                }
            }
        }

        p ^= 1;
        tile = ntile;
    }
}

// ---------------------------------------------------------------------------
extern "C" void kernel_launch(void* const* d_in, const int* in_sizes, int n_in,
                              void* d_out, int out_size) {
    const float* x     = (const float*)d_in[0];
    const float* h     = (const float*)d_in[1];
    const float* W_a   = (const float*)d_in[2];
    const float* W_g   = (const float*)d_in[3];
    const float* b_a   = (const float*)d_in[4];
    const float* b_g   = (const float*)d_in[5];
    const float* gamma = (const float*)d_in[6];
    const float* beta  = (const float*)d_in[7];
    float* out = (float*)d_out;

    static int nsm = 0;
    if (nsm == 0) {
        int dev = 0, v = 0;
        nsm = 148;
        if (cudaGetDevice(&dev) == cudaSuccess &&
            cudaDeviceGetAttribute(&v, cudaDevAttrMultiProcessorCount, dev) == cudaSuccess &&
            v > 0)
            nsm = v;
        cudaFuncSetAttribute(adaaff_kernel,
                             cudaFuncAttributeMaxDynamicSharedMemorySize, SMEM_TOTAL);
    }

    prep_w_kernel<<<256, 256>>>(W_a, W_g);
    adaaff_kernel<<<nsm, 512, SMEM_TOTAL>>>(x, h, b_a, b_g, gamma, beta, out);
}

// round 9
// speedup vs baseline: 1.0983x; 1.0437x over previous
#include <cuda_runtime.h>
#include <cuda_fp16.h>
#include <cstdint>

// ----------------------------------------------------------------------------
// AdaAffcell, dual-group persistent kernel (sm_103 base ISA: HMMA mma.sync).
//   hx = [h, x] (B x 256); g = hx W_g^T + b_g ; z = hx W_a^T + b_a
//   h~ = sigmoid(g)*tanh(z) + (1-sigmoid(g))*z ; out = LN(h~)*gamma + beta
//
// 512 threads = 2 independent groups of 8 warps (group = wid>>3; warps of both
// groups interleave across SMSPs). Each group runs its own persistent
// double-buffered loop over 32-row tiles with group-local named barriers, so
// one group's MMA (L1-heavy) overlaps the other's LDG/epilogue (DRAM/MUFU).
// Per-group warp layout wm=1, wn=8: warp = 32 rows x (16 g-cols + 16 z-cols);
// B tile read once per 32 rows. W (fp16 [256][264]) resident in SMEM per CTA.
// ----------------------------------------------------------------------------

#define NROWS  524288
#define GTILE  32
#define NTILES (NROWS / GTILE)     // 16384
#define EPSV   1e-5f

__device__ __align__(16) __half g_Wimg[256 * 264];

// SMEM layout (bytes)
#define SMEM_W     0               // fp16 [256][264] = 135168
#define SMEM_A     135168          // 4 buffers (group,parity) of 32x264 fp16 = 16896 each
#define SMEM_BG    202752          // f32 [128]
#define SMEM_BA    203264
#define SMEM_GAM   203776
#define SMEM_BET   204288
#define SMEM_PS    204800          // float2 [2 groups][2 parity][32][9] = 9216
#define SMEM_TOTAL 214016

#define BAR_SYNC(id, cnt) asm volatile("bar.sync %0, %1;" :: "r"(id), "r"(cnt) : "memory")

static __device__ __forceinline__ uint32_t smem_u32(const void* p) {
    uint32_t a;
    asm("{ .reg .u64 t; cvta.to.shared.u64 t, %1; cvt.u32.u64 %0, t; }"
        : "=r"(a) : "l"(p));
    return a;
}

static __device__ __forceinline__ float tanh_fast(float v) {
    float r;
    asm("tanh.approx.f32 %0, %1;" : "=f"(r) : "f"(v));
    return r;
}

#define LDSM4(r0, r1, r2, r3, addr)                                              \
    asm volatile("ldmatrix.sync.aligned.m8n8.x4.shared.b16 {%0,%1,%2,%3}, [%4];" \
                 : "=r"(r0), "=r"(r1), "=r"(r2), "=r"(r3) : "r"(addr))

#define MMA16816(c, a0, a1, a2, a3, b0, b1)                                  \
    asm volatile("mma.sync.aligned.m16n8k16.row.col.f32.f16.f16.f32 "        \
                 "{%0,%1,%2,%3}, {%4,%5,%6,%7}, {%8,%9}, {%0,%1,%2,%3};"     \
                 : "+f"((c)[0]), "+f"((c)[1]), "+f"((c)[2]), "+f"((c)[3])    \
                 : "r"(a0), "r"(a1), "r"(a2), "r"(a3), "r"(b0), "r"(b1))

// ---------------------------------------------------------------------------
__global__ void prep_w_kernel(const float* __restrict__ Wa, const float* __restrict__ Wg) {
    int i = blockIdx.x * 256 + threadIdx.x;   // 0..65535
    int n = i >> 8;
    int k = i & 255;
    float v = (n < 128) ? Wg[n * 256 + k] : Wa[(n - 128) * 256 + k];
    g_Wimg[n * 264 + k] = __float2half_rn(v);
}

// ---------------------------------------------------------------------------
__global__ void __launch_bounds__(512, 1) adaaff_kernel(
    const float* __restrict__ x, const float* __restrict__ h,
    const float* __restrict__ b_a, const float* __restrict__ b_g,
    const float* __restrict__ gamma, const float* __restrict__ beta,
    float* __restrict__ out)
{
    extern __shared__ __align__(16) char smem[];
    const uint32_t smem_base = smem_u32(smem);
    const int tid  = threadIdx.x;
    const int lane = tid & 31;
    const int wid  = tid >> 5;
    const int g    = wid >> 3;     // group 0/1
    const int wn   = wid & 7;      // 16-feature block within group (0..7)
    const int tig  = lane & 3;
    const int gq   = lane >> 2;
    const int gtid = tid & 255;    // thread id within group
    const int barid = 1 + g;

    // ---- one-time setup: vectors + W tile (all 512 threads) ----
    if (tid < 128) {
        *(float*)(smem + SMEM_BG  + tid * 4) = b_g[tid];
        *(float*)(smem + SMEM_BA  + tid * 4) = b_a[tid];
        *(float*)(smem + SMEM_GAM + tid * 4) = gamma[tid];
        *(float*)(smem + SMEM_BET + tid * 4) = beta[tid];
    }
    {
        const uint4* src = (const uint4*)g_Wimg;
        uint4* dst = (uint4*)(smem + SMEM_W);
        for (int i = tid; i < 8448; i += 512) dst[i] = src[i];
    }
    __syncthreads();

    // staging coords (group-local): i = gtid + jj*256 -> m = (gtid>>5)+jj*8
    const int sm0 = gtid >> 5;             // 0..7
    const int sk0 = (gtid & 31) << 2;

    // ldmatrix lane addressing (offsets into a 32x264 fp16 tile)
    uint32_t a_off[2];
    #pragma unroll
    for (int i = 0; i < 2; i++) {
        int r  = 16 * i + (lane & 15);
        int kq = (lane >> 4) * 8;
        a_off[i] = (uint32_t)(r * 264 + kq) * 2;
    }
    uint32_t b_addr[2];
    #pragma unroll
    for (int j2 = 0; j2 < 2; j2++) {
        int n  = wn * 16 + j2 * 128 + (lane & 7) + ((lane >> 4) & 1) * 8;
        int kq = ((lane >> 3) & 1) * 8;
        b_addr[j2] = smem_base + SMEM_W + (uint32_t)(n * 264 + kq) * 2;
    }

    float* s_bg  = (float*)(smem + SMEM_BG);
    float* s_ba  = (float*)(smem + SMEM_BA);
    float* s_gam = (float*)(smem + SMEM_GAM);
    float* s_bet = (float*)(smem + SMEM_BET);

    float4 rh4[4], rx4[4];

    // ---- prologue: group g stages tile (blockIdx.x*2 + g) into buffer (g,0) ----
    int t = blockIdx.x * 2 + g;
    const int tstep = gridDim.x * 2;
    if (t < NTILES) {
        const size_t r0 = (size_t)t * GTILE;
        #pragma unroll
        for (int jj = 0; jj < 4; jj++) {
            const size_t m = r0 + sm0 + jj * 8;
            rh4[jj] = *(const float4*)&h[m * 128 + sk0];
            rx4[jj] = *(const float4*)&x[m * 128 + sk0];
        }
        __half* sA = (__half*)(smem + SMEM_A + (g * 2) * 16896);
        #pragma unroll
        for (int jj = 0; jj < 4; jj++) {
            const int m = sm0 + jj * 8;
            __half2 p0 = __floats2half2_rn(rh4[jj].x, rh4[jj].y);
            __half2 p1 = __floats2half2_rn(rh4[jj].z, rh4[jj].w);
            *(uint2*)&sA[m * 264 + sk0] = make_uint2(*(uint32_t*)&p0, *(uint32_t*)&p1);
            __half2 q0 = __floats2half2_rn(rx4[jj].x, rx4[jj].y);
            __half2 q1 = __floats2half2_rn(rx4[jj].z, rx4[jj].w);
            *(uint2*)&sA[m * 264 + 128 + sk0] = make_uint2(*(uint32_t*)&q0, *(uint32_t*)&q1);
        }
    }
    BAR_SYNC(barid, 256);

    int p = 0;
    while (t < NTILES) {
        const int nt = t + tstep;
        const bool has_next = (nt < NTILES);

        // ---- 1. issue next tile's GMEM loads (covered by MMA below) ----
        if (has_next) {
            const size_t r0 = (size_t)nt * GTILE;
            #pragma unroll
            for (int jj = 0; jj < 4; jj++) {
                const size_t m = r0 + sm0 + jj * 8;
                rh4[jj] = *(const float4*)&h[m * 128 + sk0];
                rx4[jj] = *(const float4*)&x[m * 128 + sk0];
            }
        }

        // ---- 2. MMA on buffer (g,p) ----
        // c[i][j]: i = m16 block (rows 16i..); j 0,1 = g-cols n8, j 2,3 = z-cols
        const uint32_t a_base = smem_base + SMEM_A + (uint32_t)(g * 2 + p) * 16896;
        float c[2][4][4];
        #pragma unroll
        for (int i = 0; i < 2; i++)
            #pragma unroll
            for (int j = 0; j < 4; j++)
                #pragma unroll
                for (int e = 0; e < 4; e++) c[i][j][e] = 0.0f;

        #pragma unroll
        for (int s = 0; s < 16; s++) {
            const uint32_t ko = (uint32_t)s * 32;
            uint32_t ar[2][4], br[2][4];
            #pragma unroll
            for (int i = 0; i < 2; i++)
                LDSM4(ar[i][0], ar[i][1], ar[i][2], ar[i][3], a_base + a_off[i] + ko);
            #pragma unroll
            for (int j2 = 0; j2 < 2; j2++)
                LDSM4(br[j2][0], br[j2][1], br[j2][2], br[j2][3], b_addr[j2] + ko);
            #pragma unroll
            for (int i = 0; i < 2; i++) {
                #pragma unroll
                for (int j = 0; j < 4; j++) {
                    const int j2  = j >> 1;
                    const int sub = (j & 1) * 2;
                    MMA16816(c[i][j], ar[i][0], ar[i][1], ar[i][2], ar[i][3],
                             br[j2][sub], br[j2][sub + 1]);
                }
            }
        }

        // ---- 3. publish next tile into spare buffer (g,1-p) ----
        if (has_next) {
            __half* sA = (__half*)(smem + SMEM_A + (uint32_t)(g * 2 + (1 - p)) * 16896);
            #pragma unroll
            for (int jj = 0; jj < 4; jj++) {
                const int m = sm0 + jj * 8;
                __half2 p0 = __floats2half2_rn(rh4[jj].x, rh4[jj].y);
                __half2 p1 = __floats2half2_rn(rh4[jj].z, rh4[jj].w);
                *(uint2*)&sA[m * 264 + sk0] = make_uint2(*(uint32_t*)&p0, *(uint32_t*)&p1);
                __half2 q0 = __floats2half2_rn(rx4[jj].x, rx4[jj].y);
                __half2 q1 = __floats2half2_rn(rx4[jj].z, rx4[jj].w);
                *(uint2*)&sA[m * 264 + 128 + sk0] = make_uint2(*(uint32_t*)&q0, *(uint32_t*)&q1);
            }
        }

        // ---- 4. activation + row partials ----
        float rsum[4] = {0.f, 0.f, 0.f, 0.f};
        float rsq[4]  = {0.f, 0.f, 0.f, 0.f};
        #pragma unroll
        for (int i = 0; i < 2; i++) {
            #pragma unroll
            for (int j = 0; j < 2; j++) {
                const int f0 = wn * 16 + j * 8 + 2 * tig;
                #pragma unroll
                for (int rh = 0; rh < 2; rh++) {
                    #pragma unroll
                    for (int e = 0; e < 2; e++) {
                        const int f = f0 + e;
                        float gv = c[i][j][rh * 2 + e] + s_bg[f];
                        float zv = c[i][j + 2][rh * 2 + e] + s_ba[f];
                        float al = 0.5f + 0.5f * tanh_fast(0.5f * gv);   // sigmoid
                        float ht = al * tanh_fast(zv) + (1.0f - al) * zv;
                        c[i][j][rh * 2 + e] = ht;
                        rsum[i * 2 + rh] += ht;
                        rsq[i * 2 + rh]  += ht * ht;
                    }
                }
            }
        }

        float2* s_ps = (float2*)(smem + SMEM_PS) + (g * 2 + p) * 288;  // [32][9] float2
        #pragma unroll
        for (int r = 0; r < 4; r++) {
            float sv = rsum[r], qv = rsq[r];
            sv += __shfl_xor_sync(0xffffffffu, sv, 1);
            qv += __shfl_xor_sync(0xffffffffu, qv, 1);
            sv += __shfl_xor_sync(0xffffffffu, sv, 2);
            qv += __shfl_xor_sync(0xffffffffu, qv, 2);
            if (tig == 0) {
                const int rowl = 16 * (r >> 1) + 8 * (r & 1) + gq;
                s_ps[rowl * 9 + wn] = make_float2(sv, qv);
            }
        }
        BAR_SYNC(barid, 256);          // psum ready AND spare-A published

        // ---- 5. normalize + store (inline mu/rstd via quad-split partials) ----
        {
            const size_t r0 = (size_t)t * GTILE;
            #pragma unroll
            for (int i = 0; i < 2; i++) {
                #pragma unroll
                for (int rh = 0; rh < 2; rh++) {
                    const int rowl = 16 * i + 8 * rh + gq;
                    // quad lanes split the 8 partials: lane tig loads w=2tig,2tig+1
                    float2 v0 = s_ps[rowl * 9 + 2 * tig];
                    float2 v1 = s_ps[rowl * 9 + 2 * tig + 1];
                    float sv = v0.x + v1.x;
                    float qv = v0.y + v1.y;
                    sv += __shfl_xor_sync(0xffffffffu, sv, 1);
                    qv += __shfl_xor_sync(0xffffffffu, qv, 1);
                    sv += __shfl_xor_sync(0xffffffffu, sv, 2);
                    qv += __shfl_xor_sync(0xffffffffu, qv, 2);
                    const float mu = sv * (1.0f / 128.0f);
                    const float rs = rsqrtf(qv * (1.0f / 128.0f) - mu * mu + EPSV);
                    #pragma unroll
                    for (int j = 0; j < 2; j++) {
                        const int f0 = wn * 16 + j * 8 + 2 * tig;
                        float2 v;
                        v.x = (c[i][j][rh * 2 + 0] - mu) * rs * s_gam[f0]     + s_bet[f0];
                        v.y = (c[i][j][rh * 2 + 1] - mu) * rs * s_gam[f0 + 1] + s_bet[f0 + 1];
                        *(float2*)&out[(r0 + rowl) * 128 + f0] = v;
                    }
                }
            }
        }

        p ^= 1;
        t = nt;
    }
}

// ---------------------------------------------------------------------------
extern "C" void kernel_launch(void* const* d_in, const int* in_sizes, int n_in,
                              void* d_out, int out_size) {
    const float* x     = (const float*)d_in[0];
    const float* h     = (const float*)d_in[1];
    const float* W_a   = (const float*)d_in[2];
    const float* W_g   = (const float*)d_in[3];
    const float* b_a   = (const float*)d_in[4];
    const float* b_g   = (const float*)d_in[5];
    const float* gamma = (const float*)d_in[6];
    const float* beta  = (const float*)d_in[7];
    float* out = (float*)d_out;

    static int nsm = 0;
    if (nsm == 0) {
        int dev = 0, v = 0;
        nsm = 148;
        if (cudaGetDevice(&dev) == cudaSuccess &&
            cudaDeviceGetAttribute(&v, cudaDevAttrMultiProcessorCount, dev) == cudaSuccess &&
            v > 0)
            nsm = v;
        cudaFuncSetAttribute(adaaff_kernel,
                             cudaFuncAttributeMaxDynamicSharedMemorySize, SMEM_TOTAL);
    }

    prep_w_kernel<<<256, 256>>>(W_a, W_g);
    adaaff_kernel<<<nsm, 512, SMEM_TOTAL>>>(x, h, b_a, b_g, gamma, beta, out);
}